// round 15
// baseline (speedup 1.0000x reference)
#include <cuda_runtime.h>
#include <cuda_bf16.h>
#include <cstdint>

#define FLT_MAX_ 3.402823466e38f
#define NEG_INF __int_as_float(0xff800000)

// ---------------- scratch (device globals; no allocs allowed) ---------------
__device__ __nv_bfloat16 g_Ahi[4096 * 1024];   // X split, later ctx split
__device__ __nv_bfloat16 g_Alo[4096 * 1024];
__device__ __nv_bfloat16 g_WThi[4 * 1024 * 1024];  // 4 transposed weights
__device__ __nv_bfloat16 g_WTlo[4 * 1024 * 1024];
__device__ __nv_bfloat16 g_QKVhi[3 * 4096 * 1024];
__device__ __nv_bfloat16 g_QKVlo[3 * 4096 * 1024];

// ---------------- helpers (sm_80-era PTX only; no 'a' features) -------------
__device__ __forceinline__ uint32_t smem_u32(const void* p) {
    uint32_t a;
    asm("{ .reg .u64 t; cvta.to.shared.u64 t, %1; cvt.u32.u64 %0, t; }"
        : "=r"(a) : "l"(p));
    return a;
}
__device__ __forceinline__ uint32_t sw128(uint32_t off) {
    return off ^ ((off >> 3) & 0x70);
}
__device__ __forceinline__ void ldsm4(uint32_t* r, uint32_t addr) {
    asm volatile("ldmatrix.sync.aligned.m8n8.x4.shared.b16 {%0,%1,%2,%3}, [%4];"
                 : "=r"(r[0]), "=r"(r[1]), "=r"(r[2]), "=r"(r[3]) : "r"(addr));
}
__device__ __forceinline__ void ldsm4t(uint32_t* r, uint32_t addr) {
    asm volatile("ldmatrix.sync.aligned.m8n8.x4.trans.shared.b16 {%0,%1,%2,%3}, [%4];"
                 : "=r"(r[0]), "=r"(r[1]), "=r"(r[2]), "=r"(r[3]) : "r"(addr));
}
__device__ __forceinline__ void mma16816(float* d, const uint32_t* a,
                                         const uint32_t* b) {
    asm volatile(
        "mma.sync.aligned.m16n8k16.row.col.f32.bf16.bf16.f32 "
        "{%0,%1,%2,%3}, {%4,%5,%6,%7}, {%8,%9}, {%0,%1,%2,%3};"
        : "+f"(d[0]), "+f"(d[1]), "+f"(d[2]), "+f"(d[3])
        : "r"(a[0]), "r"(a[1]), "r"(a[2]), "r"(a[3]), "r"(b[0]), "r"(b[1]));
}
__device__ __forceinline__ void cpasync16(uint32_t dst, const void* src) {
    asm volatile("cp.async.cg.shared.global [%0], [%1], 16;" :: "r"(dst), "l"(src));
}
#define CP_COMMIT() asm volatile("cp.async.commit_group;" ::: "memory")
#define CP_WAIT1() asm volatile("cp.async.wait_group 1;" ::: "memory")
#define CP_WAIT0() asm volatile("cp.async.wait_group 0;" ::: "memory")

__device__ __forceinline__ float ex2(float x) {
    float y;
    asm("ex2.approx.f32 %0, %1;" : "=f"(y) : "f"(x));
    return y;
}
__device__ __forceinline__ uint32_t packbf2(float lo, float hi) {
    uint32_t r;
    asm("cvt.rn.bf16x2.f32 %0, %1, %2;" : "=r"(r) : "f"(hi), "f"(lo));
    return r;
}
__device__ __forceinline__ void split2(float x0, float x1, uint32_t& hi,
                                       uint32_t& lo) {
    hi = packbf2(x0, x1);
    float h0 = __uint_as_float(hi << 16);
    float h1 = __uint_as_float(hi & 0xffff0000u);
    lo = packbf2(x0 - h0, x1 - h1);
}

// ---------------------------------------------------------------------------
// split fp32 -> bf16 hi/lo (same layout)
// ---------------------------------------------------------------------------
__global__ __launch_bounds__(256)
void split_rows(const float* __restrict__ src, __nv_bfloat16* __restrict__ hi,
                __nv_bfloat16* __restrict__ lo, int n4) {
    int i = blockIdx.x * 256 + threadIdx.x;
    if (i >= n4) return;
    float4 v = ((const float4*)src)[i];
    uint32_t h0, l0, h1, l1;
    split2(v.x, v.y, h0, l0);
    split2(v.z, v.w, h1, l1);
    ((uint32_t*)hi)[i * 2 + 0] = h0;
    ((uint32_t*)hi)[i * 2 + 1] = h1;
    ((uint32_t*)lo)[i * 2 + 0] = l0;
    ((uint32_t*)lo)[i * 2 + 1] = l1;
}

// ---------------------------------------------------------------------------
// transpose + split all 4 weights in one launch (z selects the weight)
// ---------------------------------------------------------------------------
__global__ __launch_bounds__(256)
void transpose_split4(const float* __restrict__ W0, const float* __restrict__ W1,
                      const float* __restrict__ W2, const float* __restrict__ W3,
                      __nv_bfloat16* __restrict__ th,
                      __nv_bfloat16* __restrict__ tl) {
    __shared__ float s[32][33];
    const int z = blockIdx.z;
    const float* W = (z == 0) ? W0 : (z == 1) ? W1 : (z == 2) ? W2 : W3;
    th += (size_t)z * 1048576;
    tl += (size_t)z * 1048576;
    const int n0 = blockIdx.x * 32, k0 = blockIdx.y * 32;
    const int tx = threadIdx.x, ty = threadIdx.y;  // 32 x 8
    #pragma unroll
    for (int i = 0; i < 4; i++)
        s[ty + 8 * i][tx] = W[(size_t)(k0 + ty + 8 * i) * 1024 + n0 + tx];
    __syncthreads();
    #pragma unroll
    for (int i = 0; i < 4; i++) {
        int n = ty + 8 * i;
        float v = s[tx][n];
        __nv_bfloat16 h = __float2bfloat16(v);
        __nv_bfloat16 l = __float2bfloat16(v - __bfloat162float(h));
        size_t o = (size_t)(n0 + n) * 1024 + k0 + tx;
        th[o] = h;
        tl[o] = l;
    }
}

// ---------------------------------------------------------------------------
// HMMA bf16x3 GEMM (R4 config: KC=64, SW128, 1 CTA/SM) + z weight slicing.
//   qsc: extra output scale applied ONLY to the wz==0 bf16 output slice.
// ---------------------------------------------------------------------------
#define GBUF 65536
#define GEMM_SMEM (2 * GBUF)

__global__ __launch_bounds__(256, 1)
void gemm_hmma(const __nv_bfloat16* __restrict__ Ahi,
               const __nv_bfloat16* __restrict__ Alo,
               const __nv_bfloat16* __restrict__ Whi,
               const __nv_bfloat16* __restrict__ Wlo,
               float* __restrict__ Cf,
               __nv_bfloat16* __restrict__ Chi,
               __nv_bfloat16* __restrict__ Clo,
               float qsc) {
    extern __shared__ char smem[];
    const uint32_t sb = smem_u32(smem);
    const int tid = threadIdx.x, wid = tid >> 5, lane = tid & 31;
    const int bn = blockIdx.x * 128, bm = blockIdx.y * 128;
    const int wz = blockIdx.z;
    const int warp_m = (wid & 1) * 64, warp_n = (wid >> 1) * 32;

    const __nv_bfloat16* Bhi = Whi + (size_t)wz * 1048576;
    const __nv_bfloat16* Blo = Wlo + (size_t)wz * 1048576;

    const uint4* Asrc[2] = {(const uint4*)(Ahi + (size_t)bm * 1024),
                            (const uint4*)(Alo + (size_t)bm * 1024)};
    const uint4* Bsrc[2] = {(const uint4*)(Bhi + (size_t)bn * 1024),
                            (const uint4*)(Blo + (size_t)bn * 1024)};

    const int lrow = tid >> 3, lcol = tid & 7;
    const uint32_t ldst = sw128(lrow * 128 + lcol * 16);

    float acc[4][4][4];
    #pragma unroll
    for (int i = 0; i < 4; i++)
        #pragma unroll
        for (int j = 0; j < 4; j++)
            #pragma unroll
            for (int r = 0; r < 4; r++) acc[i][j][r] = 0.f;

    const int arow = warp_m + (lane & 15);
    const int acb = (lane >> 4) << 4;
    const int brow = warp_n + ((lane >> 4) & 1) * 8 + (lane & 7);
    const int bcb = ((lane >> 3) & 1) * 16;

    auto load_chunk = [&](int c) {
        const uint32_t base = sb + (c & 1) * GBUF;
        const int kc8 = c * 8;
        #pragma unroll
        for (int pr = 0; pr < 2; pr++)
            #pragma unroll
            for (int p = 0; p < 4; p++)
                cpasync16(base + pr * 16384 + (ldst + p * 4096),
                          Asrc[pr] + (size_t)(lrow + p * 32) * 128 + kc8 + lcol);
        #pragma unroll
        for (int pr = 0; pr < 2; pr++)
            #pragma unroll
            for (int p = 0; p < 4; p++)
                cpasync16(base + 32768 + pr * 16384 + (ldst + p * 4096),
                          Bsrc[pr] + (size_t)(lrow + p * 32) * 128 + kc8 + lcol);
        CP_COMMIT();
    };

    load_chunk(0);
    for (int c = 0; c < 16; c++) {
        if (c + 1 < 16) { load_chunk(c + 1); CP_WAIT1(); }
        else CP_WAIT0();
        __syncthreads();

        const uint32_t base = sb + (c & 1) * GBUF;
        #pragma unroll
        for (int k16 = 0; k16 < 4; k16++) {
            uint32_t a_hi[4][4], a_lo[4][4], b_hi[2][4], b_lo[2][4];
            const int acolb = k16 * 32 + acb;
            const int bcolb = k16 * 32 + bcb;
            #pragma unroll
            for (int mi = 0; mi < 4; mi++) {
                uint32_t off = (uint32_t)(arow + mi * 16) * 128 + acolb;
                ldsm4(a_hi[mi], base + sw128(off));
                ldsm4(a_lo[mi], base + 16384 + sw128(off));
            }
            #pragma unroll
            for (int nh = 0; nh < 2; nh++) {
                uint32_t off = (uint32_t)(brow + nh * 16) * 128 + bcolb;
                ldsm4(b_hi[nh], base + 32768 + sw128(off));
                ldsm4(b_lo[nh], base + 49152 + sw128(off));
            }
            #pragma unroll
            for (int mi = 0; mi < 4; mi++)
                #pragma unroll
                for (int ni = 0; ni < 4; ni++) {
                    const uint32_t* bh = &b_hi[ni >> 1][(ni & 1) * 2];
                    const uint32_t* bl = &b_lo[ni >> 1][(ni & 1) * 2];
                    mma16816(acc[mi][ni], a_hi[mi], bh);
                    mma16816(acc[mi][ni], a_hi[mi], bl);
                    mma16816(acc[mi][ni], a_lo[mi], bh);
                }
        }
        __syncthreads();
    }

    const float sc = (wz == 0) ? qsc : 1.0f;
    #pragma unroll
    for (int mi = 0; mi < 4; mi++) {
        const int r0 = bm + warp_m + mi * 16 + (lane >> 2);
        #pragma unroll
        for (int ni = 0; ni < 4; ni++) {
            const int c0 = bn + warp_n + ni * 8 + (lane & 3) * 2;
            if (Cf) {
                *(float2*)(Cf + (size_t)r0 * 1024 + c0) =
                    make_float2(acc[mi][ni][0], acc[mi][ni][1]);
                *(float2*)(Cf + (size_t)(r0 + 8) * 1024 + c0) =
                    make_float2(acc[mi][ni][2], acc[mi][ni][3]);
            } else {
                __nv_bfloat16* Ch = Chi + (size_t)wz * 4194304;
                __nv_bfloat16* Cl = Clo + (size_t)wz * 4194304;
                uint32_t hi, lo;
                split2(acc[mi][ni][0] * sc, acc[mi][ni][1] * sc, hi, lo);
                *(uint32_t*)(Ch + (size_t)r0 * 1024 + c0) = hi;
                *(uint32_t*)(Cl + (size_t)r0 * 1024 + c0) = lo;
                split2(acc[mi][ni][2] * sc, acc[mi][ni][3] * sc, hi, lo);
                *(uint32_t*)(Ch + (size_t)(r0 + 8) * 1024 + c0) = hi;
                *(uint32_t*)(Cl + (size_t)(r0 + 8) * 1024 + c0) = lo;
            }
        }
    }
}

// ---------------------------------------------------------------------------
// HMMA flash attention, bf16x3, S-AHEAD SOFTWARE PIPELINE:
//   iter t computes S(t+1) (tensor) interleaved with softmax(t) (ALU/MUFU),
//   then PV(t). KV32 tiles in a 3-deep smem ring (load issued before wait).
//   All R12 slims kept (pre-scaled Q, no clamp, float mask bias, log2 ex2).
//   CTA: 64 q rows, 4 warps, 128 thr, 2 CTAs/SM.
//   smem: Qhi 8K | Qlo 8K | 3 x 16K KV ring | maskbias 8K = 73728
// ---------------------------------------------------------------------------
#define ATT_SMEM (16384 + 49152 + 8192)
#define SOFT_SC 0.180336880f      // 0.125 * log2(e)

__global__ __launch_bounds__(128, 2)
void attn_hmma(const __nv_bfloat16* __restrict__ Qhi,
               const __nv_bfloat16* __restrict__ Qlo,
               const __nv_bfloat16* __restrict__ Khi,
               const __nv_bfloat16* __restrict__ Klo,
               const __nv_bfloat16* __restrict__ Vhi,
               const __nv_bfloat16* __restrict__ Vlo,
               const int* __restrict__ mask,
               __nv_bfloat16* __restrict__ Chi,
               __nv_bfloat16* __restrict__ Clo) {
    extern __shared__ char smem[];
    const uint32_t sb = smem_u32(smem);
    const int tid = threadIdx.x, wid = tid >> 5, lane = tid & 31;
    const int h = blockIdx.y, b = blockIdx.z;
    const int q0 = blockIdx.x * 64;

    const uint32_t sQ = 0;
    const uint32_t sKV = 16384;
    const uint32_t sM = 65536;

    const size_t hd = (size_t)h * 64;
    const __nv_bfloat16* Qh = Qhi + ((size_t)b * 2048 + q0) * 1024 + hd;
    const __nv_bfloat16* Ql = Qlo + ((size_t)b * 2048 + q0) * 1024 + hd;
    const __nv_bfloat16* Kh = Khi + (size_t)b * 2048 * 1024 + hd;
    const __nv_bfloat16* Kl = Klo + (size_t)b * 2048 * 1024 + hd;
    const __nv_bfloat16* Vh = Vhi + (size_t)b * 2048 * 1024 + hd;
    const __nv_bfloat16* Vl = Vlo + (size_t)b * 2048 * 1024 + hd;

    // KV tile 32 into given ring slot: Kh 4K | Kl 4K | Vh 4K | Vl 4K
    auto load_tile_to = [&](uint32_t base, int t) {
        const int kv0 = t * 32;
        #pragma unroll
        for (int p = 0; p < 2; p++) {
            int g = tid + p * 128;
            int row = g >> 3, col = g & 7;   // row 0..31
            uint32_t d = sw128(row * 128 + col * 16);
            size_t so = (size_t)(kv0 + row) * 1024 + col * 8;
            cpasync16(base + d, Kh + so);
            cpasync16(base + 4096 + d, Kl + so);
            cpasync16(base + 8192 + d, Vh + so);
            cpasync16(base + 12288 + d, Vl + so);
        }
        CP_COMMIT();
    };

    // Q tile (group), then KV tiles 0 and 1 (groups)
    #pragma unroll
    for (int p = 0; p < 4; p++) {
        int g = tid + p * 128;
        int row = g >> 3, col = g & 7;
        uint32_t d = sw128(row * 128 + col * 16);
        cpasync16(sb + sQ + d, Qh + (size_t)row * 1024 + col * 8);
        cpasync16(sb + sQ + 8192 + d, Ql + (size_t)row * 1024 + col * 8);
    }
    CP_COMMIT();

    uint32_t bufA = sb + sKV;            // tile t
    uint32_t bufB = bufA + 16384;        // tile t+1
    uint32_t bufC = bufB + 16384;        // tile t+2 target
    load_tile_to(bufA, 0);
    load_tile_to(bufB, 1);

    // mask -> float bias (once)
    {
        float* mb = (float*)(smem + sM);
        #pragma unroll
        for (int p = 0; p < 16; p++) {
            int i = tid + p * 128;
            mb[i] = mask[b * 2048 + i] ? 0.f : NEG_INF;
        }
    }

    const int qrow = 16 * wid + (lane & 15);
    const uint32_t qcb = (lane >> 4) * 16;
    const int krow = ((lane >> 4) & 1) * 8 + (lane & 7);
    const uint32_t kcb = ((lane >> 3) & 1) * 16;
    const int vrow = (lane & 7) + ((lane >> 3) & 1) * 8;
    const uint32_t vcb = ((lane >> 4) & 1) * 16;
    const int cb = (lane & 3) * 2;

    float m0 = NEG_INF, m1 = NEG_INF, l0 = 0.f, l1 = 0.f;
    float o[8][4];
    #pragma unroll
    for (int i = 0; i < 8; i++)
        #pragma unroll
        for (int j = 0; j < 4; j++) o[i][j] = 0.f;

    uint32_t qh[4][4], ql[4][4];
    float s[4][4], snext[4][4];

    // S = Q K^T (bf16x3) for a given K buffer into dst
    auto computeS = [&](float (*dst)[4], uint32_t kb) {
        #pragma unroll
        for (int i = 0; i < 4; i++)
            #pragma unroll
            for (int j = 0; j < 4; j++) dst[i][j] = 0.f;
        #pragma unroll
        for (int k16 = 0; k16 < 4; k16++) {
            #pragma unroll
            for (int nb = 0; nb < 2; nb++) {
                uint32_t kh4[4], kl4[4];
                uint32_t off = sw128((uint32_t)(nb * 16 + krow) * 128 + k16 * 32 + kcb);
                ldsm4(kh4, kb + off);
                ldsm4(kl4, kb + 4096 + off);
                mma16816(dst[2 * nb], qh[k16], kh4);
                mma16816(dst[2 * nb], qh[k16], kl4);
                mma16816(dst[2 * nb], ql[k16], kh4);
                mma16816(dst[2 * nb + 1], qh[k16], kh4 + 2);
                mma16816(dst[2 * nb + 1], qh[k16], kl4 + 2);
                mma16816(dst[2 * nb + 1], ql[k16], kh4 + 2);
            }
        }
    };

    // Prologue: wait Q + tile0 (leave tile1 in flight), sync, frags, S(0)
    CP_WAIT1();
    __syncthreads();
    #pragma unroll
    for (int k16 = 0; k16 < 4; k16++) {
        uint32_t off = sw128((uint32_t)qrow * 128 + k16 * 32 + qcb);
        ldsm4(qh[k16], sb + sQ + off);
        ldsm4(ql[k16], sb + sQ + 8192 + off);
    }
    computeS(s, bufA);

    for (int t = 0; t < 64; t++) {
        // stage tile t+2 into the free slot, then ensure tile t+1 resident
        if (t <= 61) { load_tile_to(bufC, t + 2); CP_WAIT1(); }
        else if (t == 62) CP_WAIT0();
        __syncthreads();   // tile t+1 visible to all warps

        // S(t+1) MMAs (tensor) + softmax(t) (ALU/MUFU) — independent streams
        if (t < 63) computeS(snext, bufB);

        const float* mkf = (const float*)(smem + sM) + t * 32;
        float rm0 = NEG_INF, rm1 = NEG_INF;
        #pragma unroll
        for (int nt = 0; nt < 4; nt++) {
            float b0 = mkf[8 * nt + cb], b1 = mkf[8 * nt + cb + 1];
            s[nt][0] += b0;
            s[nt][1] += b1;
            s[nt][2] += b0;
            s[nt][3] += b1;
            rm0 = fmaxf(rm0, fmaxf(s[nt][0], s[nt][1]));
            rm1 = fmaxf(rm1, fmaxf(s[nt][2], s[nt][3]));
        }
        rm0 = fmaxf(rm0, __shfl_xor_sync(0xffffffffu, rm0, 1));
        rm0 = fmaxf(rm0, __shfl_xor_sync(0xffffffffu, rm0, 2));
        rm1 = fmaxf(rm1, __shfl_xor_sync(0xffffffffu, rm1, 1));
        rm1 = fmaxf(rm1, __shfl_xor_sync(0xffffffffu, rm1, 2));

        float mn0 = fmaxf(m0, rm0), mn1 = fmaxf(m1, rm1);
        float a0 = ex2(m0 - mn0), a1 = ex2(m1 - mn1);
        float rs0 = 0.f, rs1 = 0.f;
        #pragma unroll
        for (int nt = 0; nt < 4; nt++) {
            s[nt][0] = ex2(s[nt][0] - mn0);
            s[nt][1] = ex2(s[nt][1] - mn0);
            s[nt][2] = ex2(s[nt][2] - mn1);
            s[nt][3] = ex2(s[nt][3] - mn1);
            rs0 += s[nt][0] + s[nt][1];
            rs1 += s[nt][2] + s[nt][3];
        }
        rs0 += __shfl_xor_sync(0xffffffffu, rs0, 1);
        rs0 += __shfl_xor_sync(0xffffffffu, rs0, 2);
        rs1 += __shfl_xor_sync(0xffffffffu, rs1, 1);
        rs1 += __shfl_xor_sync(0xffffffffu, rs1, 2);
        m0 = mn0; m1 = mn1;
        l0 = l0 * a0 + rs0; l1 = l1 * a1 + rs1;
        #pragma unroll
        for (int dt = 0; dt < 8; dt++) {
            o[dt][0] *= a0; o[dt][1] *= a0;
            o[dt][2] *= a1; o[dt][3] *= a1;
        }

        // O += P V (P register-resident, bf16x3), V from tile t (bufA)
        const uint32_t vb = bufA + 8192;
        #pragma unroll
        for (int c = 0; c < 2; c++) {
            uint32_t ahi[4], alo[4];
            split2(s[2 * c][0], s[2 * c][1], ahi[0], alo[0]);
            split2(s[2 * c][2], s[2 * c][3], ahi[1], alo[1]);
            split2(s[2 * c + 1][0], s[2 * c + 1][1], ahi[2], alo[2]);
            split2(s[2 * c + 1][2], s[2 * c + 1][3], ahi[3], alo[3]);
            #pragma unroll
            for (int db = 0; db < 4; db++) {
                uint32_t vh4[4], vl4[4];
                uint32_t off = sw128((uint32_t)(c * 16 + vrow) * 128 + db * 32 + vcb);
                ldsm4t(vh4, vb + off);
                ldsm4t(vl4, vb + 4096 + off);
                mma16816(o[2 * db], ahi, vh4);
                mma16816(o[2 * db], ahi, vl4);
                mma16816(o[2 * db], alo, vh4);
                mma16816(o[2 * db + 1], ahi, vh4 + 2);
                mma16816(o[2 * db + 1], ahi, vl4 + 2);
                mma16816(o[2 * db + 1], alo, vh4 + 2);
            }
        }
        __syncthreads();   // all warps done reading bufA before its reuse

        #pragma unroll
        for (int i = 0; i < 4; i++)
            #pragma unroll
            for (int j = 0; j < 4; j++) s[i][j] = snext[i][j];
        uint32_t tmp = bufA; bufA = bufB; bufB = bufC; bufC = tmp;
    }

    const float i0 = 1.f / l0, i1 = 1.f / l1;
    const size_t r0 = (size_t)b * 2048 + q0 + 16 * wid + (lane >> 2);
    #pragma unroll
    for (int dt = 0; dt < 8; dt++) {
        size_t col = hd + 8 * dt + cb;
        uint32_t hi, lo;
        split2(o[dt][0] * i0, o[dt][1] * i0, hi, lo);
        *(uint32_t*)(Chi + r0 * 1024 + col) = hi;
        *(uint32_t*)(Clo + r0 * 1024 + col) = lo;
        split2(o[dt][2] * i1, o[dt][3] * i1, hi, lo);
        *(uint32_t*)(Chi + (r0 + 8) * 1024 + col) = hi;
        *(uint32_t*)(Clo + (r0 + 8) * 1024 + col) = lo;
    }
}

// ---------------------------------------------------------------------------
extern "C" void kernel_launch(void* const* d_in, const int* in_sizes, int n_in,
                              void* d_out, int out_size) {
    const float* X    = (const float*)d_in[0];
    const int*   mask = (const int*)d_in[1];
    const float* W_Q  = (const float*)d_in[2];
    const float* W_K  = (const float*)d_in[3];
    const float* W_V  = (const float*)d_in[4];
    const float* W_O  = (const float*)d_in[5];
    float* out = (float*)d_out;

    __nv_bfloat16 *ahi, *alo, *wth, *wtl, *qkvh, *qkvl;
    cudaGetSymbolAddress((void**)&ahi, g_Ahi);
    cudaGetSymbolAddress((void**)&alo, g_Alo);
    cudaGetSymbolAddress((void**)&wth, g_WThi);
    cudaGetSymbolAddress((void**)&wtl, g_WTlo);
    cudaGetSymbolAddress((void**)&qkvh, g_QKVhi);
    cudaGetSymbolAddress((void**)&qkvl, g_QKVlo);

    cudaFuncSetAttribute(gemm_hmma, cudaFuncAttributeMaxDynamicSharedMemorySize,
                         GEMM_SMEM);
    cudaFuncSetAttribute(attn_hmma, cudaFuncAttributeMaxDynamicSharedMemorySize,
                         ATT_SMEM);

    const int n4 = 4096 * 1024 / 4;

    // X -> hi/lo  +  all 4 weight transposes (one launch)
    split_rows<<<n4 / 256, 256>>>(X, ahi, alo, n4);
    transpose_split4<<<dim3(32, 32, 4), dim3(32, 8)>>>(W_Q, W_K, W_V, W_O,
                                                       wth, wtl);

    // Q/K/V projections in ONE launch; Q slice pre-scaled by 0.125*log2(e)
    gemm_hmma<<<dim3(8, 32, 3), 256, GEMM_SMEM>>>(ahi, alo, wth, wtl,
                                                  nullptr, qkvh, qkvl, SOFT_SC);

    // attention: 64-row q tiles, KV32 triple-buffer ring, S-ahead pipeline
    dim3 ga(32, 16, 2);
    attn_hmma<<<ga, 128, ATT_SMEM>>>(qkvh, qkvl,
                                     qkvh + (size_t)4194304, qkvl + (size_t)4194304,
                                     qkvh + (size_t)8388608, qkvl + (size_t)8388608,
                                     mask, ahi, alo);

    // output projection: weight slot 3, fp32 out
    gemm_hmma<<<dim3(8, 32, 1), 256, GEMM_SMEM>>>(ahi, alo,
                                                  wth + (size_t)3 * 1048576,
                                                  wtl + (size_t)3 * 1048576,
                                                  out, nullptr, nullptr, 1.0f);
}

// round 16
// speedup vs baseline: 1.0590x; 1.0590x over previous
#include <cuda_runtime.h>
#include <cuda_bf16.h>
#include <cstdint>

#define FLT_MAX_ 3.402823466e38f
#define NEG_INF __int_as_float(0xff800000)

// ---------------- scratch (device globals; no allocs allowed) ---------------
__device__ __nv_bfloat16 g_Ahi[4096 * 1024];   // X split, later ctx split
__device__ __nv_bfloat16 g_Alo[4096 * 1024];
__device__ __nv_bfloat16 g_WThi[4 * 1024 * 1024];  // 4 transposed weights
__device__ __nv_bfloat16 g_WTlo[4 * 1024 * 1024];
__device__ __nv_bfloat16 g_QKVhi[3 * 4096 * 1024];
__device__ __nv_bfloat16 g_QKVlo[3 * 4096 * 1024];

// ---------------- helpers (sm_80-era PTX only; no 'a' features) -------------
__device__ __forceinline__ uint32_t smem_u32(const void* p) {
    uint32_t a;
    asm("{ .reg .u64 t; cvta.to.shared.u64 t, %1; cvt.u32.u64 %0, t; }"
        : "=r"(a) : "l"(p));
    return a;
}
__device__ __forceinline__ uint32_t sw128(uint32_t off) {
    return off ^ ((off >> 3) & 0x70);
}
__device__ __forceinline__ void ldsm4(uint32_t* r, uint32_t addr) {
    asm volatile("ldmatrix.sync.aligned.m8n8.x4.shared.b16 {%0,%1,%2,%3}, [%4];"
                 : "=r"(r[0]), "=r"(r[1]), "=r"(r[2]), "=r"(r[3]) : "r"(addr));
}
__device__ __forceinline__ void ldsm4t(uint32_t* r, uint32_t addr) {
    asm volatile("ldmatrix.sync.aligned.m8n8.x4.trans.shared.b16 {%0,%1,%2,%3}, [%4];"
                 : "=r"(r[0]), "=r"(r[1]), "=r"(r[2]), "=r"(r[3]) : "r"(addr));
}
__device__ __forceinline__ void mma16816(float* d, const uint32_t* a,
                                         const uint32_t* b) {
    asm volatile(
        "mma.sync.aligned.m16n8k16.row.col.f32.bf16.bf16.f32 "
        "{%0,%1,%2,%3}, {%4,%5,%6,%7}, {%8,%9}, {%0,%1,%2,%3};"
        : "+f"(d[0]), "+f"(d[1]), "+f"(d[2]), "+f"(d[3])
        : "r"(a[0]), "r"(a[1]), "r"(a[2]), "r"(a[3]), "r"(b[0]), "r"(b[1]));
}
__device__ __forceinline__ void cpasync16(uint32_t dst, const void* src) {
    asm volatile("cp.async.cg.shared.global [%0], [%1], 16;" :: "r"(dst), "l"(src));
}
#define CP_COMMIT() asm volatile("cp.async.commit_group;" ::: "memory")
#define CP_WAIT1() asm volatile("cp.async.wait_group 1;" ::: "memory")
#define CP_WAIT0() asm volatile("cp.async.wait_group 0;" ::: "memory")

__device__ __forceinline__ float ex2(float x) {
    float y;
    asm("ex2.approx.f32 %0, %1;" : "=f"(y) : "f"(x));
    return y;
}
__device__ __forceinline__ uint32_t packbf2(float lo, float hi) {
    uint32_t r;
    asm("cvt.rn.bf16x2.f32 %0, %1, %2;" : "=r"(r) : "f"(hi), "f"(lo));
    return r;
}
__device__ __forceinline__ void split2(float x0, float x1, uint32_t& hi,
                                       uint32_t& lo) {
    hi = packbf2(x0, x1);
    float h0 = __uint_as_float(hi << 16);
    float h1 = __uint_as_float(hi & 0xffff0000u);
    lo = packbf2(x0 - h0, x1 - h1);
}

// ---------------------------------------------------------------------------
// split fp32 -> bf16 hi/lo (same layout)
// ---------------------------------------------------------------------------
__global__ __launch_bounds__(256)
void split_rows(const float* __restrict__ src, __nv_bfloat16* __restrict__ hi,
                __nv_bfloat16* __restrict__ lo, int n4) {
    int i = blockIdx.x * 256 + threadIdx.x;
    if (i >= n4) return;
    float4 v = ((const float4*)src)[i];
    uint32_t h0, l0, h1, l1;
    split2(v.x, v.y, h0, l0);
    split2(v.z, v.w, h1, l1);
    ((uint32_t*)hi)[i * 2 + 0] = h0;
    ((uint32_t*)hi)[i * 2 + 1] = h1;
    ((uint32_t*)lo)[i * 2 + 0] = l0;
    ((uint32_t*)lo)[i * 2 + 1] = l1;
}

// ---------------------------------------------------------------------------
// transpose + split all 4 weights in one launch (z selects the weight)
// ---------------------------------------------------------------------------
__global__ __launch_bounds__(256)
void transpose_split4(const float* __restrict__ W0, const float* __restrict__ W1,
                      const float* __restrict__ W2, const float* __restrict__ W3,
                      __nv_bfloat16* __restrict__ th,
                      __nv_bfloat16* __restrict__ tl) {
    __shared__ float s[32][33];
    const int z = blockIdx.z;
    const float* W = (z == 0) ? W0 : (z == 1) ? W1 : (z == 2) ? W2 : W3;
    th += (size_t)z * 1048576;
    tl += (size_t)z * 1048576;
    const int n0 = blockIdx.x * 32, k0 = blockIdx.y * 32;
    const int tx = threadIdx.x, ty = threadIdx.y;  // 32 x 8
    #pragma unroll
    for (int i = 0; i < 4; i++)
        s[ty + 8 * i][tx] = W[(size_t)(k0 + ty + 8 * i) * 1024 + n0 + tx];
    __syncthreads();
    #pragma unroll
    for (int i = 0; i < 4; i++) {
        int n = ty + 8 * i;
        float v = s[tx][n];
        __nv_bfloat16 h = __float2bfloat16(v);
        __nv_bfloat16 l = __float2bfloat16(v - __bfloat162float(h));
        size_t o = (size_t)(n0 + n) * 1024 + k0 + tx;
        th[o] = h;
        tl[o] = l;
    }
}

// ---------------------------------------------------------------------------
// HMMA bf16x3 GEMM, 128x64 tile, KC=64, SW128, 2 CTAs/SM (phase overlap).
//   8 warps: 2 (m) x 4 (n); warp tile 64x16. z selects weight/output slice.
//   smem/buffer: Ahi 16K | Alo 16K | Bhi 8K | Blo 8K = 48K; x2 = 96K.
//   qsc: extra output scale applied ONLY to the wz==0 bf16 output slice.
// ---------------------------------------------------------------------------
#define GBUF 49152
#define GEMM_SMEM (2 * GBUF)

__global__ __launch_bounds__(256, 2)
void gemm_hmma(const __nv_bfloat16* __restrict__ Ahi,
               const __nv_bfloat16* __restrict__ Alo,
               const __nv_bfloat16* __restrict__ Whi,
               const __nv_bfloat16* __restrict__ Wlo,
               float* __restrict__ Cf,
               __nv_bfloat16* __restrict__ Chi,
               __nv_bfloat16* __restrict__ Clo,
               float qsc) {
    extern __shared__ char smem[];
    const uint32_t sb = smem_u32(smem);
    const int tid = threadIdx.x, wid = tid >> 5, lane = tid & 31;
    const int bn = blockIdx.x * 64, bm = blockIdx.y * 128;
    const int wz = blockIdx.z;
    const int warp_m = (wid & 1) * 64, warp_n = (wid >> 1) * 16;

    const __nv_bfloat16* Bhi = Whi + (size_t)wz * 1048576;
    const __nv_bfloat16* Blo = Wlo + (size_t)wz * 1048576;

    const uint4* Asrc[2] = {(const uint4*)(Ahi + (size_t)bm * 1024),
                            (const uint4*)(Alo + (size_t)bm * 1024)};
    const uint4* Bsrc[2] = {(const uint4*)(Bhi + (size_t)bn * 1024),
                            (const uint4*)(Blo + (size_t)bn * 1024)};

    float acc[4][2][4];
    #pragma unroll
    for (int i = 0; i < 4; i++)
        #pragma unroll
        for (int j = 0; j < 2; j++)
            #pragma unroll
            for (int r = 0; r < 4; r++) acc[i][j][r] = 0.f;

    const int arow = warp_m + (lane & 15);
    const int acb = (lane >> 4) << 4;
    const int brow = warp_n + ((lane >> 4) & 1) * 8 + (lane & 7);
    const int bcb = ((lane >> 3) & 1) * 16;

    auto load_chunk = [&](int c) {
        const uint32_t base = sb + (c & 1) * GBUF;
        const int kc8 = c * 8;
        // A: 128 rows x 8 granules, hi/lo
        #pragma unroll
        for (int pr = 0; pr < 2; pr++)
            #pragma unroll
            for (int p = 0; p < 4; p++) {
                int g = tid + p * 256;
                int row = g >> 3, col = g & 7;
                cpasync16(base + pr * 16384 + sw128(row * 128 + col * 16),
                          Asrc[pr] + (size_t)row * 128 + kc8 + col);
            }
        // B: 64 rows x 8 granules, hi/lo
        #pragma unroll
        for (int pr = 0; pr < 2; pr++)
            #pragma unroll
            for (int p = 0; p < 2; p++) {
                int g = tid + p * 256;
                int row = g >> 3, col = g & 7;
                cpasync16(base + 32768 + pr * 8192 + sw128(row * 128 + col * 16),
                          Bsrc[pr] + (size_t)row * 128 + kc8 + col);
            }
        CP_COMMIT();
    };

    load_chunk(0);
    for (int c = 0; c < 16; c++) {
        if (c + 1 < 16) { load_chunk(c + 1); CP_WAIT1(); }
        else CP_WAIT0();
        __syncthreads();

        const uint32_t base = sb + (c & 1) * GBUF;
        #pragma unroll
        for (int k16 = 0; k16 < 4; k16++) {
            uint32_t a_hi[4][4], a_lo[4][4], b_hi[4], b_lo[4];
            const int acolb = k16 * 32 + acb;
            const int bcolb = k16 * 32 + bcb;
            #pragma unroll
            for (int mi = 0; mi < 4; mi++) {
                uint32_t off = (uint32_t)(arow + mi * 16) * 128 + acolb;
                ldsm4(a_hi[mi], base + sw128(off));
                ldsm4(a_lo[mi], base + 16384 + sw128(off));
            }
            {
                uint32_t off = (uint32_t)brow * 128 + bcolb;
                ldsm4(b_hi, base + 32768 + sw128(off));
                ldsm4(b_lo, base + 40960 + sw128(off));
            }
            #pragma unroll
            for (int mi = 0; mi < 4; mi++)
                #pragma unroll
                for (int ni = 0; ni < 2; ni++) {
                    const uint32_t* bh = &b_hi[ni * 2];
                    const uint32_t* bl = &b_lo[ni * 2];
                    mma16816(acc[mi][ni], a_hi[mi], bh);
                    mma16816(acc[mi][ni], a_hi[mi], bl);
                    mma16816(acc[mi][ni], a_lo[mi], bh);
                }
        }
        __syncthreads();
    }

    const float sc = (wz == 0) ? qsc : 1.0f;
    #pragma unroll
    for (int mi = 0; mi < 4; mi++) {
        const int r0 = bm + warp_m + mi * 16 + (lane >> 2);
        #pragma unroll
        for (int ni = 0; ni < 2; ni++) {
            const int c0 = bn + warp_n + ni * 8 + (lane & 3) * 2;
            if (Cf) {
                *(float2*)(Cf + (size_t)r0 * 1024 + c0) =
                    make_float2(acc[mi][ni][0], acc[mi][ni][1]);
                *(float2*)(Cf + (size_t)(r0 + 8) * 1024 + c0) =
                    make_float2(acc[mi][ni][2], acc[mi][ni][3]);
            } else {
                __nv_bfloat16* Ch = Chi + (size_t)wz * 4194304;
                __nv_bfloat16* Cl = Clo + (size_t)wz * 4194304;
                uint32_t hi, lo;
                split2(acc[mi][ni][0] * sc, acc[mi][ni][1] * sc, hi, lo);
                *(uint32_t*)(Ch + (size_t)r0 * 1024 + c0) = hi;
                *(uint32_t*)(Cl + (size_t)r0 * 1024 + c0) = lo;
                split2(acc[mi][ni][2] * sc, acc[mi][ni][3] * sc, hi, lo);
                *(uint32_t*)(Ch + (size_t)(r0 + 8) * 1024 + c0) = hi;
                *(uint32_t*)(Cl + (size_t)(r0 + 8) * 1024 + c0) = lo;
            }
        }
    }
}

// ---------------------------------------------------------------------------
// HMMA flash attention, bf16x3.  R12 EXACT (best measured: 251us):
//   3 CTAs/SM, KV32 double buffer, pre-scaled Q, no clamp, float mask bias,
//   log2 softmax, hoisted qh+ql.
//   smem: Qhi 8K | Qlo 8K | 2 x 16K KV | maskbias 8K = 57344
// ---------------------------------------------------------------------------
#define ATT_SMEM (16384 + 32768 + 8192)
#define SOFT_SC 0.180336880f      // 0.125 * log2(e)

__global__ __launch_bounds__(128, 3)
void attn_hmma(const __nv_bfloat16* __restrict__ Qhi,
               const __nv_bfloat16* __restrict__ Qlo,
               const __nv_bfloat16* __restrict__ Khi,
               const __nv_bfloat16* __restrict__ Klo,
               const __nv_bfloat16* __restrict__ Vhi,
               const __nv_bfloat16* __restrict__ Vlo,
               const int* __restrict__ mask,
               __nv_bfloat16* __restrict__ Chi,
               __nv_bfloat16* __restrict__ Clo) {
    extern __shared__ char smem[];
    const uint32_t sb = smem_u32(smem);
    const int tid = threadIdx.x, wid = tid >> 5, lane = tid & 31;
    const int h = blockIdx.y, b = blockIdx.z;
    const int q0 = blockIdx.x * 64;

    const uint32_t sQ = 0;
    const uint32_t sKV = 16384;
    const uint32_t sM = 49152;

    const size_t hd = (size_t)h * 64;
    const __nv_bfloat16* Qh = Qhi + ((size_t)b * 2048 + q0) * 1024 + hd;
    const __nv_bfloat16* Ql = Qlo + ((size_t)b * 2048 + q0) * 1024 + hd;
    const __nv_bfloat16* Kh = Khi + (size_t)b * 2048 * 1024 + hd;
    const __nv_bfloat16* Kl = Klo + (size_t)b * 2048 * 1024 + hd;
    const __nv_bfloat16* Vh = Vhi + (size_t)b * 2048 * 1024 + hd;
    const __nv_bfloat16* Vl = Vlo + (size_t)b * 2048 * 1024 + hd;

    #pragma unroll
    for (int p = 0; p < 4; p++) {
        int g = tid + p * 128;
        int row = g >> 3, col = g & 7;
        uint32_t d = sw128(row * 128 + col * 16);
        cpasync16(sb + sQ + d, Qh + (size_t)row * 1024 + col * 8);
        cpasync16(sb + sQ + 8192 + d, Ql + (size_t)row * 1024 + col * 8);
    }
    CP_COMMIT();

    {
        float* mb = (float*)(smem + sM);
        #pragma unroll
        for (int p = 0; p < 16; p++) {
            int i = tid + p * 128;
            mb[i] = mask[b * 2048 + i] ? 0.f : NEG_INF;
        }
    }

    auto load_tile = [&](int t) {
        const uint32_t base = sb + sKV + (t & 1) * 16384;
        const int kv0 = t * 32;
        #pragma unroll
        for (int p = 0; p < 2; p++) {
            int g = tid + p * 128;
            int row = g >> 3, col = g & 7;
            uint32_t d = sw128(row * 128 + col * 16);
            size_t so = (size_t)(kv0 + row) * 1024 + col * 8;
            cpasync16(base + d, Kh + so);
            cpasync16(base + 4096 + d, Kl + so);
            cpasync16(base + 8192 + d, Vh + so);
            cpasync16(base + 12288 + d, Vl + so);
        }
        CP_COMMIT();
    };

    const int qrow = 16 * wid + (lane & 15);
    const uint32_t qcb = (lane >> 4) * 16;
    const int krow = ((lane >> 4) & 1) * 8 + (lane & 7);
    const uint32_t kcb = ((lane >> 3) & 1) * 16;
    const int vrow = (lane & 7) + ((lane >> 3) & 1) * 8;
    const uint32_t vcb = ((lane >> 4) & 1) * 16;
    const int cb = (lane & 3) * 2;

    float m0 = NEG_INF, m1 = NEG_INF, l0 = 0.f, l1 = 0.f;
    float o[8][4];
    #pragma unroll
    for (int i = 0; i < 8; i++)
        #pragma unroll
        for (int j = 0; j < 4; j++) o[i][j] = 0.f;

    uint32_t qh[4][4], ql[4][4];

    load_tile(0);
    for (int t = 0; t < 64; t++) {
        if (t < 63) load_tile(t + 1);
        if (t < 63) CP_WAIT1(); else CP_WAIT0();
        __syncthreads();

        if (t == 0) {
            #pragma unroll
            for (int k16 = 0; k16 < 4; k16++) {
                uint32_t off = sw128((uint32_t)qrow * 128 + k16 * 32 + qcb);
                ldsm4(qh[k16], sb + sQ + off);
                ldsm4(ql[k16], sb + sQ + 8192 + off);
            }
        }

        const uint32_t kb = sb + sKV + (t & 1) * 16384;
        const uint32_t vb = kb + 8192;

        float s[4][4];
        #pragma unroll
        for (int i = 0; i < 4; i++)
            #pragma unroll
            for (int j = 0; j < 4; j++) s[i][j] = 0.f;

        #pragma unroll
        for (int k16 = 0; k16 < 4; k16++) {
            #pragma unroll
            for (int nb = 0; nb < 2; nb++) {
                uint32_t kh4[4], kl4[4];
                uint32_t off = sw128((uint32_t)(nb * 16 + krow) * 128 + k16 * 32 + kcb);
                ldsm4(kh4, kb + off);
                ldsm4(kl4, kb + 4096 + off);
                mma16816(s[2 * nb], qh[k16], kh4);
                mma16816(s[2 * nb], qh[k16], kl4);
                mma16816(s[2 * nb], ql[k16], kh4);
                mma16816(s[2 * nb + 1], qh[k16], kh4 + 2);
                mma16816(s[2 * nb + 1], qh[k16], kl4 + 2);
                mma16816(s[2 * nb + 1], ql[k16], kh4 + 2);
            }
        }

        const float* mkf = (const float*)(smem + sM) + t * 32;
        float rm0 = NEG_INF, rm1 = NEG_INF;
        #pragma unroll
        for (int nt = 0; nt < 4; nt++) {
            float b0 = mkf[8 * nt + cb], b1 = mkf[8 * nt + cb + 1];
            s[nt][0] += b0;
            s[nt][1] += b1;
            s[nt][2] += b0;
            s[nt][3] += b1;
            rm0 = fmaxf(rm0, fmaxf(s[nt][0], s[nt][1]));
            rm1 = fmaxf(rm1, fmaxf(s[nt][2], s[nt][3]));
        }
        rm0 = fmaxf(rm0, __shfl_xor_sync(0xffffffffu, rm0, 1));
        rm0 = fmaxf(rm0, __shfl_xor_sync(0xffffffffu, rm0, 2));
        rm1 = fmaxf(rm1, __shfl_xor_sync(0xffffffffu, rm1, 1));
        rm1 = fmaxf(rm1, __shfl_xor_sync(0xffffffffu, rm1, 2));

        float mn0 = fmaxf(m0, rm0), mn1 = fmaxf(m1, rm1);
        float a0 = ex2(m0 - mn0), a1 = ex2(m1 - mn1);
        float rs0 = 0.f, rs1 = 0.f;
        #pragma unroll
        for (int nt = 0; nt < 4; nt++) {
            s[nt][0] = ex2(s[nt][0] - mn0);
            s[nt][1] = ex2(s[nt][1] - mn0);
            s[nt][2] = ex2(s[nt][2] - mn1);
            s[nt][3] = ex2(s[nt][3] - mn1);
            rs0 += s[nt][0] + s[nt][1];
            rs1 += s[nt][2] + s[nt][3];
        }
        rs0 += __shfl_xor_sync(0xffffffffu, rs0, 1);
        rs0 += __shfl_xor_sync(0xffffffffu, rs0, 2);
        rs1 += __shfl_xor_sync(0xffffffffu, rs1, 1);
        rs1 += __shfl_xor_sync(0xffffffffu, rs1, 2);
        m0 = mn0; m1 = mn1;
        l0 = l0 * a0 + rs0; l1 = l1 * a1 + rs1;
        #pragma unroll
        for (int dt = 0; dt < 8; dt++) {
            o[dt][0] *= a0; o[dt][1] *= a0;
            o[dt][2] *= a1; o[dt][3] *= a1;
        }

        #pragma unroll
        for (int c = 0; c < 2; c++) {
            uint32_t ahi[4], alo[4];
            split2(s[2 * c][0], s[2 * c][1], ahi[0], alo[0]);
            split2(s[2 * c][2], s[2 * c][3], ahi[1], alo[1]);
            split2(s[2 * c + 1][0], s[2 * c + 1][1], ahi[2], alo[2]);
            split2(s[2 * c + 1][2], s[2 * c + 1][3], ahi[3], alo[3]);
            #pragma unroll
            for (int db = 0; db < 4; db++) {
                uint32_t vh4[4], vl4[4];
                uint32_t off = sw128((uint32_t)(c * 16 + vrow) * 128 + db * 32 + vcb);
                ldsm4t(vh4, vb + off);
                ldsm4t(vl4, vb + 4096 + off);
                mma16816(o[2 * db], ahi, vh4);
                mma16816(o[2 * db], ahi, vl4);
                mma16816(o[2 * db], alo, vh4);
                mma16816(o[2 * db + 1], ahi, vh4 + 2);
                mma16816(o[2 * db + 1], ahi, vl4 + 2);
                mma16816(o[2 * db + 1], alo, vh4 + 2);
            }
        }
        __syncthreads();
    }

    const float i0 = 1.f / l0, i1 = 1.f / l1;
    const size_t r0 = (size_t)b * 2048 + q0 + 16 * wid + (lane >> 2);
    #pragma unroll
    for (int dt = 0; dt < 8; dt++) {
        size_t col = hd + 8 * dt + cb;
        uint32_t hi, lo;
        split2(o[dt][0] * i0, o[dt][1] * i0, hi, lo);
        *(uint32_t*)(Chi + r0 * 1024 + col) = hi;
        *(uint32_t*)(Clo + r0 * 1024 + col) = lo;
        split2(o[dt][2] * i1, o[dt][3] * i1, hi, lo);
        *(uint32_t*)(Chi + (r0 + 8) * 1024 + col) = hi;
        *(uint32_t*)(Clo + (r0 + 8) * 1024 + col) = lo;
    }
}

// ---------------------------------------------------------------------------
extern "C" void kernel_launch(void* const* d_in, const int* in_sizes, int n_in,
                              void* d_out, int out_size) {
    const float* X    = (const float*)d_in[0];
    const int*   mask = (const int*)d_in[1];
    const float* W_Q  = (const float*)d_in[2];
    const float* W_K  = (const float*)d_in[3];
    const float* W_V  = (const float*)d_in[4];
    const float* W_O  = (const float*)d_in[5];
    float* out = (float*)d_out;

    __nv_bfloat16 *ahi, *alo, *wth, *wtl, *qkvh, *qkvl;
    cudaGetSymbolAddress((void**)&ahi, g_Ahi);
    cudaGetSymbolAddress((void**)&alo, g_Alo);
    cudaGetSymbolAddress((void**)&wth, g_WThi);
    cudaGetSymbolAddress((void**)&wtl, g_WTlo);
    cudaGetSymbolAddress((void**)&qkvh, g_QKVhi);
    cudaGetSymbolAddress((void**)&qkvl, g_QKVlo);

    cudaFuncSetAttribute(gemm_hmma, cudaFuncAttributeMaxDynamicSharedMemorySize,
                         GEMM_SMEM);
    cudaFuncSetAttribute(attn_hmma, cudaFuncAttributeMaxDynamicSharedMemorySize,
                         ATT_SMEM);

    const int n4 = 4096 * 1024 / 4;

    // X -> hi/lo  +  all 4 weight transposes (one launch)
    split_rows<<<n4 / 256, 256>>>(X, ahi, alo, n4);
    transpose_split4<<<dim3(32, 32, 4), dim3(32, 8)>>>(W_Q, W_K, W_V, W_O,
                                                       wth, wtl);

    // Q/K/V projections in ONE launch; Q slice pre-scaled by 0.125*log2(e)
    gemm_hmma<<<dim3(16, 32, 3), 256, GEMM_SMEM>>>(ahi, alo, wth, wtl,
                                                   nullptr, qkvh, qkvl, SOFT_SC);

    // attention: R12 config (best measured)
    dim3 ga(32, 16, 2);
    attn_hmma<<<ga, 128, ATT_SMEM>>>(qkvh, qkvl,
                                     qkvh + (size_t)4194304, qkvl + (size_t)4194304,
                                     qkvh + (size_t)8388608, qkvl + (size_t)8388608,
                                     mask, ahi, alo);

    // output projection: weight slot 3, fp32 out
    gemm_hmma<<<dim3(16, 32, 1), 256, GEMM_SMEM>>>(ahi, alo,
                                                   wth + (size_t)3 * 1048576,
                                                   wtl + (size_t)3 * 1048576,
                                                   out, nullptr, nullptr, 1.0f);
}